// round 4
// baseline (speedup 1.0000x reference)
#include <cuda_runtime.h>
#include <cuda_bf16.h>
#include <math.h>
#include <stdint.h>

#define BATCH 2048
#define INPUT_DIM 256
#define UNITS 1024
#define KTOT (INPUT_DIM + UNITS)       // 1280
#define NGATE (4 * UNITS)              // 4096
#define STEPS 96
#define OUT_UNITS 256
#define OUT_ROW_STRIDE (STEPS * OUT_UNITS)  // 24576

// ---------------- persistent device scratch (__device__ globals only) ------
__device__ __nv_bfloat16 g_Wg_hi[NGATE * KTOT];   // gate weights, n-major [n'=4u+g][k]
__device__ __nv_bfloat16 g_Wg_lo[NGATE * KTOT];
__device__ __nv_bfloat16 g_Wdt_hi[OUT_UNITS * UNITS];  // proj weights, n-major [n][k]
__device__ __nv_bfloat16 g_Wdt_lo[OUT_UNITS * UNITS];
__device__ float g_bias_r[NGATE];                 // bias reordered to n'=4u+g
__device__ __nv_bfloat16 g_xh_hi[BATCH * KTOT];   // activations: cols 0-255 = x, 256.. = h
__device__ __nv_bfloat16 g_xh_lo[BATCH * KTOT];
__device__ float g_c[BATCH * UNITS];
__device__ float g_z[(size_t)BATCH * NGATE];      // gate pre-activations (32 MB)

// ---------------- helpers ---------------------------------------------------
__device__ __forceinline__ uint32_t smaddr(const void* p) {
    return (uint32_t)__cvta_generic_to_shared(p);
}
__device__ __forceinline__ void cpa16(uint32_t dst, const void* src) {
    asm volatile("cp.async.cg.shared.global [%0], [%1], 16;\n" :: "r"(dst), "l"(src));
}
__device__ __forceinline__ void cp_commit() { asm volatile("cp.async.commit_group;\n"); }
__device__ __forceinline__ uint32_t ld32s(const __nv_bfloat16* p) {
    return *reinterpret_cast<const uint32_t*>(p);
}
__device__ __forceinline__ void mma_bf16(float* d, const uint32_t* a, const uint32_t* b) {
    asm volatile(
        "mma.sync.aligned.m16n8k16.row.col.f32.bf16.bf16.f32 "
        "{%0,%1,%2,%3},{%4,%5,%6,%7},{%8,%9},{%0,%1,%2,%3};\n"
        : "+f"(d[0]), "+f"(d[1]), "+f"(d[2]), "+f"(d[3])
        : "r"(a[0]), "r"(a[1]), "r"(a[2]), "r"(a[3]), "r"(b[0]), "r"(b[1]));
}
__device__ __forceinline__ void split_bf16(float v, __nv_bfloat16* hi, __nv_bfloat16* lo) {
    __nv_bfloat16 h = __float2bfloat16(v);
    *hi = h;
    *lo = __float2bfloat16(v - __bfloat162float(h));
}

// ---------------- prep kernels (run once per launch; deterministic) ---------
__global__ __launch_bounds__(256) void prep_gate_weights(
    const float* __restrict__ Wk, const float* __restrict__ Wr)
{
    int id = blockIdx.x * 256 + threadIdx.x;            // [n'][k]
    if (id >= NGATE * KTOT) return;
    int np = id / KTOT, k = id % KTOT;
    int u = np >> 2, gg = np & 3;
    int col = gg * UNITS + u;
    float w = (k < INPUT_DIM) ? Wk[k * NGATE + col] : Wr[(k - INPUT_DIM) * NGATE + col];
    split_bf16(w, &g_Wg_hi[id], &g_Wg_lo[id]);
}

__global__ __launch_bounds__(256) void prep_proj_weights(const float* __restrict__ Wd)
{
    int id = blockIdx.x * 256 + threadIdx.x;            // [n][k]
    if (id >= OUT_UNITS * UNITS) return;
    int n = id / UNITS, k = id % UNITS;
    float w = Wd[k * OUT_UNITS + n];
    split_bf16(w, &g_Wdt_hi[id], &g_Wdt_lo[id]);
}

__global__ __launch_bounds__(256) void prep_bias(const float* __restrict__ b)
{
    int id = blockIdx.x * 256 + threadIdx.x;
    if (id >= NGATE) return;
    int u = id >> 2, gg = id & 3;
    g_bias_r[id] = b[gg * UNITS + u];
}

__global__ __launch_bounds__(256) void prep_x(const float* __restrict__ x)
{
    int id = blockIdx.x * 256 + threadIdx.x;            // 2048*256
    if (id >= BATCH * INPUT_DIM) return;
    int bb = id >> 8, c = id & 255;
    split_bf16(x[id], &g_xh_hi[bb * KTOT + c], &g_xh_lo[bb * KTOT + c]);
}

__global__ __launch_bounds__(256) void prep_h(const float* __restrict__ h0)
{
    int id = blockIdx.x * 256 + threadIdx.x;            // 2048*1024
    if (id >= BATCH * UNITS) return;
    int bb = id >> 10, u = id & 1023;
    split_bf16(h0[id], &g_xh_hi[bb * KTOT + INPUT_DIM + u],
                       &g_xh_lo[bb * KTOT + INPUT_DIM + u]);
}

// ---------------- gates GEMM: z = xh @ Wg'  (M=2048, N=4096, K=1280) --------
// block 128x128, 8 warps (4m x 2n), warp 32x64, split-bf16 3-term mma.
__global__ __launch_bounds__(256) void gates_mma()
{
    __shared__ __nv_bfloat16 sA[2][2][128][16];   // [stage][hi/lo][m][k]
    __shared__ __nv_bfloat16 sB[2][2][128][16];   // [stage][hi/lo][n][k]

    const int tid = threadIdx.x;
    const int wid = tid >> 5, lane = tid & 31;
    const int g = lane >> 2, t = lane & 3;
    const int m0 = blockIdx.x * 128, n0 = blockIdx.y * 128;
    const int wm = (wid >> 1) * 32, wn = (wid & 1) * 64;

    const int row = tid >> 1;              // 0..127
    const int half = (tid & 1) * 8;        // element offset within 16-wide k slab
    const __nv_bfloat16* gAh = g_xh_hi + (size_t)(m0 + row) * KTOT + half;
    const __nv_bfloat16* gAl = g_xh_lo + (size_t)(m0 + row) * KTOT + half;
    const __nv_bfloat16* gBh = g_Wg_hi + (size_t)(n0 + row) * KTOT + half;
    const __nv_bfloat16* gBl = g_Wg_lo + (size_t)(n0 + row) * KTOT + half;

    float acc[2][8][4];
#pragma unroll
    for (int i = 0; i < 2; i++)
#pragma unroll
        for (int j = 0; j < 8; j++)
#pragma unroll
            for (int l = 0; l < 4; l++) acc[i][j][l] = 0.0f;

    const int NS = KTOT / 16;   // 80
    // prologue: stage 0
    cpa16(smaddr(&sA[0][0][row][half]), gAh);
    cpa16(smaddr(&sA[0][1][row][half]), gAl);
    cpa16(smaddr(&sB[0][0][row][half]), gBh);
    cpa16(smaddr(&sB[0][1][row][half]), gBl);
    cp_commit();

    for (int s = 0; s < NS; s++) {
        if (s + 1 < NS) {
            int ns = (s + 1) & 1, kt = (s + 1) * 16;
            cpa16(smaddr(&sA[ns][0][row][half]), gAh + kt);
            cpa16(smaddr(&sA[ns][1][row][half]), gAl + kt);
            cpa16(smaddr(&sB[ns][0][row][half]), gBh + kt);
            cpa16(smaddr(&sB[ns][1][row][half]), gBl + kt);
            cp_commit();
            asm volatile("cp.async.wait_group 1;\n");
        } else {
            asm volatile("cp.async.wait_group 0;\n");
        }
        __syncthreads();
        const int st = s & 1;

        uint32_t ah[2][4], al[2][4];
#pragma unroll
        for (int mt = 0; mt < 2; mt++) {
            int mr = wm + mt * 16;
            ah[mt][0] = ld32s(&sA[st][0][mr + g][2 * t]);
            ah[mt][1] = ld32s(&sA[st][0][mr + g + 8][2 * t]);
            ah[mt][2] = ld32s(&sA[st][0][mr + g][2 * t + 8]);
            ah[mt][3] = ld32s(&sA[st][0][mr + g + 8][2 * t + 8]);
            al[mt][0] = ld32s(&sA[st][1][mr + g][2 * t]);
            al[mt][1] = ld32s(&sA[st][1][mr + g + 8][2 * t]);
            al[mt][2] = ld32s(&sA[st][1][mr + g][2 * t + 8]);
            al[mt][3] = ld32s(&sA[st][1][mr + g + 8][2 * t + 8]);
        }
#pragma unroll
        for (int nt = 0; nt < 8; nt++) {
            int nr = wn + nt * 8 + g;
            uint32_t bh[2], bl[2];
            bh[0] = ld32s(&sB[st][0][nr][2 * t]);
            bh[1] = ld32s(&sB[st][0][nr][2 * t + 8]);
            bl[0] = ld32s(&sB[st][1][nr][2 * t]);
            bl[1] = ld32s(&sB[st][1][nr][2 * t + 8]);
#pragma unroll
            for (int mt = 0; mt < 2; mt++) {
                mma_bf16(acc[mt][nt], ah[mt], bh);
                mma_bf16(acc[mt][nt], ah[mt], bl);
                mma_bf16(acc[mt][nt], al[mt], bh);
            }
        }
        __syncthreads();
    }

    // epilogue: store z
#pragma unroll
    for (int mt = 0; mt < 2; mt++) {
#pragma unroll
        for (int nt = 0; nt < 8; nt++) {
            int m = m0 + wm + mt * 16 + g;
            int n = n0 + wn + nt * 8 + 2 * t;
            *(float2*)&g_z[(size_t)m * NGATE + n] =
                make_float2(acc[mt][nt][0], acc[mt][nt][1]);
            *(float2*)&g_z[(size_t)(m + 8) * NGATE + n] =
                make_float2(acc[mt][nt][2], acc[mt][nt][3]);
        }
    }
}

// ---------------- elementwise LSTM cell update ------------------------------
__global__ __launch_bounds__(256) void lstm_cell(const float* __restrict__ c_in)
{
    int id = blockIdx.x * 256 + threadIdx.x;        // 2048*1024
    if (id >= BATCH * UNITS) return;
    int bb = id >> 10, u = id & 1023;
    float4 z4 = *(const float4*)&g_z[(size_t)bb * NGATE + 4 * u];
    float4 b4 = *(const float4*)&g_bias_r[4 * u];
    float zi = z4.x + b4.x, zf = z4.y + b4.y, zg = z4.z + b4.z, zo = z4.w + b4.w;
    float ii = 1.0f / (1.0f + expf(-zi));
    float ff = 1.0f / (1.0f + expf(-zf));
    float oo = 1.0f / (1.0f + expf(-zo));
    float cn = ff * c_in[id] + ii * tanhf(zg);
    float hn = oo * tanhf(cn);
    g_c[id] = cn;
    split_bf16(hn, &g_xh_hi[bb * KTOT + INPUT_DIM + u],
                   &g_xh_lo[bb * KTOT + INPUT_DIM + u]);
}

// ---------------- projection: pred = h @ Wd + bd (M=2048, N=256, K=1024) ----
// block 64x64, 4 warps (2m x 2n), warp 32x32. Writes fp32 out + bf16 next-x.
__global__ __launch_bounds__(128) void proj_mma(const float* __restrict__ bd,
                                                float* __restrict__ out_t)
{
    __shared__ __nv_bfloat16 sA[2][2][64][16];
    __shared__ __nv_bfloat16 sB[2][2][64][16];

    const int tid = threadIdx.x;
    const int wid = tid >> 5, lane = tid & 31;
    const int g = lane >> 2, t = lane & 3;
    const int m0 = blockIdx.x * 64, n0 = blockIdx.y * 64;
    const int wm = (wid >> 1) * 32, wn = (wid & 1) * 32;

    const int row = tid >> 1;          // 0..63
    const int half = (tid & 1) * 8;
    const __nv_bfloat16* gAh = g_xh_hi + (size_t)(m0 + row) * KTOT + INPUT_DIM + half;
    const __nv_bfloat16* gAl = g_xh_lo + (size_t)(m0 + row) * KTOT + INPUT_DIM + half;
    const __nv_bfloat16* gBh = g_Wdt_hi + (size_t)(n0 + row) * UNITS + half;
    const __nv_bfloat16* gBl = g_Wdt_lo + (size_t)(n0 + row) * UNITS + half;

    float acc[2][4][4];
#pragma unroll
    for (int i = 0; i < 2; i++)
#pragma unroll
        for (int j = 0; j < 4; j++)
#pragma unroll
            for (int l = 0; l < 4; l++) acc[i][j][l] = 0.0f;

    const int NS = UNITS / 16;   // 64
    cpa16(smaddr(&sA[0][0][row][half]), gAh);
    cpa16(smaddr(&sA[0][1][row][half]), gAl);
    cpa16(smaddr(&sB[0][0][row][half]), gBh);
    cpa16(smaddr(&sB[0][1][row][half]), gBl);
    cp_commit();

    for (int s = 0; s < NS; s++) {
        if (s + 1 < NS) {
            int ns = (s + 1) & 1, kt = (s + 1) * 16;
            cpa16(smaddr(&sA[ns][0][row][half]), gAh + kt);
            cpa16(smaddr(&sA[ns][1][row][half]), gAl + kt);
            cpa16(smaddr(&sB[ns][0][row][half]), gBh + kt);
            cpa16(smaddr(&sB[ns][1][row][half]), gBl + kt);
            cp_commit();
            asm volatile("cp.async.wait_group 1;\n");
        } else {
            asm volatile("cp.async.wait_group 0;\n");
        }
        __syncthreads();
        const int st = s & 1;

        uint32_t ah[2][4], al[2][4];
#pragma unroll
        for (int mt = 0; mt < 2; mt++) {
            int mr = wm + mt * 16;
            ah[mt][0] = ld32s(&sA[st][0][mr + g][2 * t]);
            ah[mt][1] = ld32s(&sA[st][0][mr + g + 8][2 * t]);
            ah[mt][2] = ld32s(&sA[st][0][mr + g][2 * t + 8]);
            ah[mt][3] = ld32s(&sA[st][0][mr + g + 8][2 * t + 8]);
            al[mt][0] = ld32s(&sA[st][1][mr + g][2 * t]);
            al[mt][1] = ld32s(&sA[st][1][mr + g + 8][2 * t]);
            al[mt][2] = ld32s(&sA[st][1][mr + g][2 * t + 8]);
            al[mt][3] = ld32s(&sA[st][1][mr + g + 8][2 * t + 8]);
        }
#pragma unroll
        for (int nt = 0; nt < 4; nt++) {
            int nr = wn + nt * 8 + g;
            uint32_t bh[2], bl[2];
            bh[0] = ld32s(&sB[st][0][nr][2 * t]);
            bh[1] = ld32s(&sB[st][0][nr][2 * t + 8]);
            bl[0] = ld32s(&sB[st][1][nr][2 * t]);
            bl[1] = ld32s(&sB[st][1][nr][2 * t + 8]);
#pragma unroll
            for (int mt = 0; mt < 2; mt++) {
                mma_bf16(acc[mt][nt], ah[mt], bh);
                mma_bf16(acc[mt][nt], ah[mt], bl);
                mma_bf16(acc[mt][nt], al[mt], bh);
            }
        }
        __syncthreads();
    }

    // epilogue: out = acc + bd; also split into next-step x (xh cols 0-255)
#pragma unroll
    for (int mt = 0; mt < 2; mt++) {
#pragma unroll
        for (int nt = 0; nt < 4; nt++) {
            int n = n0 + wn + nt * 8 + 2 * t;
            float bias0 = bd[n], bias1 = bd[n + 1];
#pragma unroll
            for (int rh = 0; rh < 2; rh++) {
                int m = m0 + wm + mt * 16 + g + rh * 8;
                float v0 = acc[mt][nt][rh * 2 + 0] + bias0;
                float v1 = acc[mt][nt][rh * 2 + 1] + bias1;
                *(float2*)&out_t[(size_t)m * OUT_ROW_STRIDE + n] = make_float2(v0, v1);
                __nv_bfloat16 h0, l0, h1, l1;
                split_bf16(v0, &h0, &l0);
                split_bf16(v1, &h1, &l1);
                *(__nv_bfloat162*)&g_xh_hi[(size_t)m * KTOT + n] =
                    __nv_bfloat162(h0, h1);
                *(__nv_bfloat162*)&g_xh_lo[(size_t)m * KTOT + n] =
                    __nv_bfloat162(l0, l1);
            }
        }
    }
}

// ---------------------------------------------------------------------------
extern "C" void kernel_launch(void* const* d_in, const int* in_sizes, int n_in,
                              void* d_out, int out_size)
{
    const float* last_input = (const float*)d_in[0];
    const float* h0 = (const float*)d_in[1];
    const float* c0 = (const float*)d_in[2];
    const float* Wk = (const float*)d_in[3];
    const float* Wr = (const float*)d_in[4];
    const float* bias = (const float*)d_in[5];
    const float* Wd = (const float*)d_in[6];
    const float* bd = (const float*)d_in[7];
    float* out = (float*)d_out;

    float* cbuf;
    cudaGetSymbolAddress((void**)&cbuf, g_c);

    prep_gate_weights<<<(NGATE * KTOT + 255) / 256, 256>>>(Wk, Wr);
    prep_proj_weights<<<(OUT_UNITS * UNITS + 255) / 256, 256>>>(Wd);
    prep_bias<<<(NGATE + 255) / 256, 256>>>(bias);
    prep_x<<<(BATCH * INPUT_DIM + 255) / 256, 256>>>(last_input);
    prep_h<<<(BATCH * UNITS + 255) / 256, 256>>>(h0);

    dim3 gates_grid(BATCH / 128, NGATE / 128);    // (16, 32)
    dim3 proj_grid(BATCH / 64, OUT_UNITS / 64);   // (32, 4)
    int lstm_blocks = (BATCH * UNITS + 255) / 256;

    for (int t = 0; t < STEPS; ++t) {
        gates_mma<<<gates_grid, 256>>>();
        lstm_cell<<<lstm_blocks, 256>>>(t == 0 ? c0 : cbuf);
        proj_mma<<<proj_grid, 128>>>(bd, out + (size_t)t * OUT_UNITS);
    }
}